// round 14
// baseline (speedup 1.0000x reference)
#include <cuda_runtime.h>
#include <cuda_bf16.h>

#define N_NODES 50000
#define N_EDGES 800000
#define CH      128
#define NGRAPH  64
#define SCAN_B  512
#define NBLK    ((N_NODES + SCAN_B - 1) / SCAN_B)   // 98
#define WPK_N   (16 * 16 * 32)                       // fragments per layer
#define N_TILES ((N_NODES + 127) / 128)              // 391
#define AH_COLS 136                                  // bf16 cols incl pad
#define AH_ELEMS (128 * AH_COLS)
#define GEMM_SMEM (2 * AH_ELEMS * 2 + WPK_N * 8)     // 69632 + 65536 = 135168
#define GEMM_GRID 148

// ---------------- scratch (__device__ globals; no allocation) ----------------
__device__ int      d_deg[N_NODES];
__device__ int      d_off[N_NODES + 1];
__device__ int      d_cur[N_NODES];
__device__ int      d_csr[N_EDGES];
__device__ int      d_tmp[N_NODES];
__device__ int      d_bsum[NBLK];
__device__ float    d_dinv[N_NODES];
__device__ int      d_gcount[NGRAPH];
__device__ unsigned d_gq[N_NODES * 32];       // g rows, int8 (4 ch per uint)
__device__ float    d_gscale[N_NODES];        // per-row dequant step
__device__ uint4    d_xb[N_NODES * CH / 8];   // x in bf16 (converted once)
__device__ uint4    d_hb[N_NODES * CH / 8];   // activations in bf16
// W pre-packed into m16n8k8 B-fragment layout, tf32
__device__ uint2    d_wpk[3 * WPK_N];

// ---------------- tf32 helpers ----------------
__device__ __forceinline__ unsigned f2tf32(float f) {
    unsigned u;
    asm("cvt.rna.tf32.f32 %0, %1;" : "=r"(u) : "f"(f));
    return u;
}

__device__ __forceinline__ void mma_tf32(float c[4], unsigned a0, unsigned a1,
                                         unsigned a2, unsigned a3,
                                         unsigned b0, unsigned b1) {
    asm volatile(
        "mma.sync.aligned.m16n8k8.row.col.f32.tf32.tf32.f32 "
        "{%0,%1,%2,%3}, {%4,%5,%6,%7}, {%8,%9}, {%0,%1,%2,%3};"
        : "+f"(c[0]), "+f"(c[1]), "+f"(c[2]), "+f"(c[3])
        : "r"(a0), "r"(a1), "r"(a2), "r"(a3), "r"(b0), "r"(b1));
}

// ---------------- setup: zero counters + pack W fragments --------------------
__global__ void k_zero_pack(const float* __restrict__ W1, const float* __restrict__ W2,
                            const float* __restrict__ W3) {
    int i = blockIdx.x * blockDim.x + threadIdx.x;
    if (i < N_NODES) d_deg[i] = 0;
    if (i < NGRAPH)  d_gcount[i] = 0;
    if (i < 3 * WPK_N) {
        int m    = i / WPK_N;
        int rem  = i - m * WPK_N;
        int ks   = rem >> 9;
        int nt   = (rem >> 5) & 15;
        int lane = rem & 31;
        int q = lane & 3, g = lane >> 2;
        const float* W = (m == 0) ? W1 : (m == 1) ? W2 : W3;
        int k = ks * 8 + q;
        int n = nt * 8 + g;
        uint2 u;
        u.x = f2tf32(W[k * CH + n]);
        u.y = f2tf32(W[(k + 4) * CH + n]);
        d_wpk[i] = u;
    }
}

// ---------------- hist + x->bf16 convert (800000 threads, exact match) -------
__global__ void k_hist(const int* __restrict__ dst, const int* __restrict__ batch,
                       const float* __restrict__ x) {
    int i = blockIdx.x * blockDim.x + threadIdx.x;
    if (i >= N_EDGES) return;
    atomicAdd(&d_deg[dst[i]], 1);
    if (i < N_NODES) atomicAdd(&d_gcount[batch[i]], 1);
    float4 v0 = ((const float4*)x)[i * 2];
    float4 v1 = ((const float4*)x)[i * 2 + 1];
    __nv_bfloat162 p0 = __floats2bfloat162_rn(v0.x, v0.y);
    __nv_bfloat162 p1 = __floats2bfloat162_rn(v0.z, v0.w);
    __nv_bfloat162 p2 = __floats2bfloat162_rn(v1.x, v1.y);
    __nv_bfloat162 p3 = __floats2bfloat162_rn(v1.z, v1.w);
    uint4 u;
    u.x = *reinterpret_cast<unsigned*>(&p0);
    u.y = *reinterpret_cast<unsigned*>(&p1);
    u.z = *reinterpret_cast<unsigned*>(&p2);
    u.w = *reinterpret_cast<unsigned*>(&p3);
    d_xb[i] = u;
}

// scanA: warp-shuffle inclusive scan (exact, 2 barriers)
__global__ void k_scanA() {
    __shared__ int wsum[16];
    int t = threadIdx.x;
    int i = blockIdx.x * SCAN_B + t;
    int v = (i < N_NODES) ? d_deg[i] : 0;
    int lane = t & 31;
#pragma unroll
    for (int o = 1; o < 32; o <<= 1) {
        int n = __shfl_up_sync(0xffffffffu, v, o);
        if (lane >= o) v += n;
    }
    if (lane == 31) wsum[t >> 5] = v;
    __syncthreads();
    if (t < 16) {
        int w = wsum[t];
#pragma unroll
        for (int o = 1; o < 16; o <<= 1) {
            int n = __shfl_up_sync(0xffffu, w, o);
            if (t >= o) w += n;
        }
        wsum[t] = w;
    }
    __syncthreads();
    if (t >= 32) v += wsum[(t >> 5) - 1];
    if (i < N_NODES) d_tmp[i] = v;
    if (t == SCAN_B - 1) d_bsum[blockIdx.x] = v;
}

// scanC with inline block-prefix over d_bsum
__global__ void k_scanC() {
    __shared__ int ws[8];
    __shared__ int bpref;
    int t = threadIdx.x;
    int myblk = blockIdx.x >> 1;
    int v = (t < myblk) ? d_bsum[t] : 0;
#pragma unroll
    for (int o = 16; o; o >>= 1) v += __shfl_down_sync(0xffffffffu, v, o);
    if ((t & 31) == 0) ws[t >> 5] = v;
    __syncthreads();
    if (t == 0) {
        int s = 0;
#pragma unroll
        for (int w = 0; w < 8; w++) s += ws[w];
        bpref = s;
    }
    __syncthreads();

    int i = blockIdx.x * 256 + t;
    if (i >= N_NODES) return;
    int incl = d_tmp[i] + bpref;
    int deg  = d_deg[i];
    d_off[i + 1] = incl;
    d_cur[i]     = incl - deg;
    d_dinv[i]    = rsqrtf((float)deg + 1.0f);
    if (i == 0) d_off[0] = 0;
}

__global__ void k_scatter(const int* __restrict__ src, const int* __restrict__ dst) {
    int e = blockIdx.x * blockDim.x + threadIdx.x;
    if (e >= N_EDGES) return;
    int p = atomicAdd(&d_cur[dst[e]], 1);
    d_csr[p] = src[e];
}

// ---------------- GEMM: persistent, B resident, A (bf16) double-buffered -----
__device__ __forceinline__ void prefetch_A(__nv_bfloat16* dstbuf, const uint4* Asrc,
                                           int m0, int tid) {
#pragma unroll
    for (int i = 0; i < 8; i++) {
        int idx = tid + 256 * i;
        int row = idx >> 4;
        int u16 = idx & 15;
        int grow = m0 + row;
        if (grow > N_NODES - 1) grow = N_NODES - 1;
        const uint4* src = Asrc + (size_t)grow * 16 + u16;
        unsigned dst = (unsigned)__cvta_generic_to_shared(dstbuf + row * AH_COLS + u16 * 8);
        asm volatile("cp.async.ca.shared.global [%0], [%1], 16;" :: "r"(dst), "l"(src));
    }
    asm volatile("cp.async.commit_group;" ::: "memory");
}

__device__ __forceinline__ unsigned short pack_q8(float v0, float v1, float inv) {
    int i0 = __float2int_rn(v0 * inv);
    int i1 = __float2int_rn(v1 * inv);
    return (unsigned short)((i0 & 0xff) | ((i1 & 0xff) << 8));
}

__global__ __launch_bounds__(256) void k_gemm_persist(int a_sel, int layer) {
    extern __shared__ __nv_bfloat16 dynsmem_h[];
    __nv_bfloat16* AsH = dynsmem_h;
    uint2* Bp = (uint2*)(dynsmem_h + 2 * AH_ELEMS);

    const uint4* Asrc = a_sel ? d_hb : d_xb;

    int tid  = threadIdx.x;
    int wid  = tid >> 5;
    int lane = tid & 31;
    int g    = lane >> 2;
    int q    = lane & 3;
    int wm   = wid * 16;

    {
        const uint4* src4 = (const uint4*)(d_wpk + (size_t)layer * WPK_N);
        uint4* dst4 = (uint4*)Bp;
#pragma unroll
        for (int i = 0; i < 16; i++) dst4[tid + 256 * i] = src4[tid + 256 * i];
    }

    int t0 = blockIdx.x;
    if (t0 < N_TILES) prefetch_A(AsH, Asrc, t0 * 128, tid);

    int buf = 0;
    unsigned short* gout = (unsigned short*)d_gq;   // row = 64 ushorts (2 int8 each)

    for (int t = t0; t < N_TILES; t += GEMM_GRID) {
        asm volatile("cp.async.wait_group 0;" ::: "memory");
        __syncthreads();

        int tn = t + GEMM_GRID;
        if (tn < N_TILES) prefetch_A(AsH + (buf ^ 1) * AH_ELEMS, Asrc, tn * 128, tid);

        const unsigned short* Ab = (const unsigned short*)(AsH + buf * AH_ELEMS);
        int m0 = t * 128;

        float acc[16][4];
#pragma unroll
        for (int nt = 0; nt < 16; nt++)
#pragma unroll
            for (int j = 0; j < 4; j++) acc[nt][j] = 0.0f;

#pragma unroll
        for (int ks = 0; ks < 16; ks++) {
            int k8 = ks * 8;
            unsigned a0 = ((unsigned)Ab[(wm + g) * AH_COLS + k8 + q])     << 16;
            unsigned a1 = ((unsigned)Ab[(wm + g + 8) * AH_COLS + k8 + q]) << 16;
            unsigned a2 = ((unsigned)Ab[(wm + g) * AH_COLS + k8 + q + 4]) << 16;
            unsigned a3 = ((unsigned)Ab[(wm + g + 8) * AH_COLS + k8 + q + 4]) << 16;
#pragma unroll
            for (int nt = 0; nt < 16; nt++) {
                uint2 b = Bp[(ks * 16 + nt) * 32 + lane];
                mma_tf32(acc[nt], a0, a1, a2, a3, b.x, b.y);
            }
        }

        int r0 = m0 + wm + g;
        int r1 = r0 + 8;
        bool v0 = (r0 < N_NODES);
        bool v1 = (r1 < N_NODES);
        float s0 = v0 ? d_dinv[r0] : 0.0f;
        float s1 = v1 ? d_dinv[r1] : 0.0f;

        // per-row absmax across the quad (lanes 4g..4g+3 hold the full row)
        float m0v = 0.0f, m1v = 0.0f;
#pragma unroll
        for (int nt = 0; nt < 16; nt++) {
            m0v = fmaxf(m0v, fmaxf(fabsf(acc[nt][0]), fabsf(acc[nt][1])));
            m1v = fmaxf(m1v, fmaxf(fabsf(acc[nt][2]), fabsf(acc[nt][3])));
        }
        m0v = fmaxf(m0v, __shfl_xor_sync(0xffffffffu, m0v, 1));
        m0v = fmaxf(m0v, __shfl_xor_sync(0xffffffffu, m0v, 2));
        m1v = fmaxf(m1v, __shfl_xor_sync(0xffffffffu, m1v, 1));
        m1v = fmaxf(m1v, __shfl_xor_sync(0xffffffffu, m1v, 2));

        float vmax0 = s0 * m0v;
        float vmax1 = s1 * m1v;
        float inv0 = (vmax0 > 0.0f) ? (127.0f * s0 / vmax0) : 0.0f;  // = 127/m0v
        float inv1 = (vmax1 > 0.0f) ? (127.0f * s1 / vmax1) : 0.0f;
        if (q == 0) {
            if (v0) d_gscale[r0] = vmax0 * (1.0f / 127.0f);
            if (v1) d_gscale[r1] = vmax1 * (1.0f / 127.0f);
        }
#pragma unroll
        for (int nt = 0; nt < 16; nt++) {
            int cu = nt * 4 + q;
            if (v0) gout[(size_t)r0 * 64 + cu] = pack_q8(acc[nt][0], acc[nt][1], inv0);
            if (v1) gout[(size_t)r1 * 64 + cu] = pack_q8(acc[nt][2], acc[nt][3], inv1);
        }

        __syncthreads();
        buf ^= 1;
    }
}

// ---------------- aggregation: h = relu(dinv_i * (g_i + Σ g_src) + b) --------
__device__ __forceinline__ void acc_g(float4& acc, int row, int lane) {
    unsigned u = __ldg(&d_gq[(size_t)row * 32 + lane]);
    float sc = __ldg(&d_gscale[row]);
    int b0 = (int)(signed char)(u & 0xff);
    int b1 = (int)(signed char)((u >> 8) & 0xff);
    int b2 = (int)(signed char)((u >> 16) & 0xff);
    int b3 = (int)(signed char)(u >> 24);
    acc.x = fmaf(sc, (float)b0, acc.x);
    acc.y = fmaf(sc, (float)b1, acc.y);
    acc.z = fmaf(sc, (float)b2, acc.z);
    acc.w = fmaf(sc, (float)b3, acc.w);
}

__global__ __launch_bounds__(256) void k_agg(const float* __restrict__ bias) {
    int gw = (blockIdx.x * blockDim.x + threadIdx.x) >> 5;
    if (gw >= N_NODES) return;
    int lane = threadIdx.x & 31;

    int beg = d_off[gw];
    int end = d_off[gw + 1];

    float4 acc = make_float4(0.f, 0.f, 0.f, 0.f);
    acc_g(acc, gw, lane);   // self term
    int j = beg;
    for (; j + 4 <= end; j += 4) {
        int s0 = d_csr[j + 0];
        int s1 = d_csr[j + 1];
        int s2 = d_csr[j + 2];
        int s3 = d_csr[j + 3];
        acc_g(acc, s0, lane);
        acc_g(acc, s1, lane);
        acc_g(acc, s2, lane);
        acc_g(acc, s3, lane);
    }
    for (; j < end; j++) acc_g(acc, d_csr[j], lane);

    float  s  = d_dinv[gw];
    float4 b4 = ((const float4*)bias)[lane];
    float rx = fmaxf(fmaf(s, acc.x, b4.x), 0.0f);
    float ry = fmaxf(fmaf(s, acc.y, b4.y), 0.0f);
    float rz = fmaxf(fmaf(s, acc.z, b4.z), 0.0f);
    float rw = fmaxf(fmaf(s, acc.w, b4.w), 0.0f);

    __nv_bfloat162 p0 = __floats2bfloat162_rn(rx, ry);
    __nv_bfloat162 p1 = __floats2bfloat162_rn(rz, rw);
    uint2 u;
    u.x = *reinterpret_cast<unsigned*>(&p0);
    u.y = *reinterpret_cast<unsigned*>(&p1);
    ((uint2*)d_hb)[(size_t)gw * 32 + lane] = u;
}

// ---------------- fused mean-pool + head (512 threads) -----------------------
__global__ __launch_bounds__(512) void k_pool_final(const float* __restrict__ Wc,
                                                    const float* __restrict__ bc,
                                                    float* __restrict__ out) {
    __shared__ float red[4][CH];
    __shared__ float pl[CH];
    __shared__ int rng[2];
    int g = blockIdx.x;
    int t = threadIdx.x;
    if (t == 0) {
        int b = 0;
        for (int j = 0; j < g; j++) b += d_gcount[j];
        rng[0] = b;
        rng[1] = b + d_gcount[g];
    }
    __syncthreads();
    int b = rng[0], e = rng[1];
    int c = t & 127, seg = t >> 7;
    const __nv_bfloat16* h = (const __nv_bfloat16*)d_hb;
    float s = 0.0f;
    for (int i = b + seg; i < e; i += 4) s += __bfloat162float(h[(size_t)i * CH + c]);
    red[seg][c] = s;
    __syncthreads();
    if (seg == 0) {
        float tot = (red[0][c] + red[1][c]) + (red[2][c] + red[3][c]);
        pl[c] = tot / fmaxf((float)(e - b), 1.0f);
    }
    __syncthreads();
    if (t < 64) {
        int o = t >> 5;
        int lane = t & 31;
        float s2 = 0.0f;
#pragma unroll
        for (int k = lane; k < CH; k += 32) s2 += pl[k] * Wc[k * 2 + o];
#pragma unroll
        for (int off = 16; off; off >>= 1) s2 += __shfl_down_sync(0xffffffffu, s2, off);
        if (lane == 0) out[g * 2 + o] = s2 + bc[o];
    }
}

// ---------------- launch -----------------------------------------------------
extern "C" void kernel_launch(void* const* d_in, const int* in_sizes, int n_in,
                              void* d_out, int out_size) {
    const float* x     = (const float*)d_in[0];
    const int*   ei    = (const int*)d_in[1];     // [2, E]: src then dst
    const int*   batch = (const int*)d_in[2];
    const float* W1 = (const float*)d_in[3];
    const float* b1 = (const float*)d_in[4];
    const float* W2 = (const float*)d_in[5];
    const float* b2 = (const float*)d_in[6];
    const float* W3 = (const float*)d_in[7];
    const float* b3 = (const float*)d_in[8];
    const float* Wc = (const float*)d_in[9];
    const float* bc = (const float*)d_in[10];
    float* out = (float*)d_out;

    const int* src = ei;
    const int* dst = ei + N_EDGES;

    cudaFuncSetAttribute(k_gemm_persist, cudaFuncAttributeMaxDynamicSharedMemorySize, GEMM_SMEM);

    int gN = (N_NODES + 255) / 256;
    int gE = (N_EDGES + 255) / 256;
    int gAgg  = (N_NODES * 32 + 255) / 256;

    k_zero_pack<<<gN, 256>>>(W1, W2, W3);
    k_hist<<<gE, 256>>>(dst, batch, x);
    k_scanA<<<NBLK, SCAN_B>>>();
    k_scanC<<<gN, 256>>>();
    k_scatter<<<gE, 256>>>(src, dst);

    // layer 1 (A = x in bf16)
    k_gemm_persist<<<GEMM_GRID, 256, GEMM_SMEM>>>(0, 0);
    k_agg<<<gAgg, 256>>>(b1);
    // layer 2
    k_gemm_persist<<<GEMM_GRID, 256, GEMM_SMEM>>>(1, 1);
    k_agg<<<gAgg, 256>>>(b2);
    // layer 3
    k_gemm_persist<<<GEMM_GRID, 256, GEMM_SMEM>>>(1, 2);
    k_agg<<<gAgg, 256>>>(b3);

    k_pool_final<<<NGRAPH, 512>>>(Wc, bc, out);
}

// round 15
// speedup vs baseline: 1.2133x; 1.2133x over previous
#include <cuda_runtime.h>
#include <cuda_bf16.h>

#define N_NODES 50000
#define N_EDGES 800000
#define CH      128
#define NGRAPH  64
#define SCAN_B  512
#define NBLK    ((N_NODES + SCAN_B - 1) / SCAN_B)   // 98
#define WPK_N   (16 * 16 * 32)                       // fragments per layer
#define N_TILES ((N_NODES + 127) / 128)              // 391
#define AH_COLS 136                                  // bf16 cols incl pad
#define AH_ELEMS (128 * AH_COLS)
#define GEMM_SMEM (2 * AH_ELEMS * 2 + WPK_N * 8)     // 69632 + 65536 = 135168
#define GEMM_GRID 148

// ---------------- scratch (__device__ globals; no allocation) ----------------
__device__ int      d_deg[N_NODES];
__device__ int      d_off[N_NODES + 1];
__device__ int      d_cur[N_NODES];
__device__ int      d_csr[N_EDGES];
__device__ int      d_tmp[N_NODES];
__device__ int      d_bsum[NBLK];
__device__ float    d_dinv[N_NODES];
__device__ int      d_gcount[NGRAPH];
__device__ uint2    d_g[N_NODES * 32];        // g = dinv * (h @ W), bf16 (4 ch per uint2)
__device__ uint4    d_xb[N_NODES * CH / 8];   // x in bf16 (converted once)
__device__ uint4    d_hb[N_NODES * CH / 8];   // activations in bf16
// W pre-packed into m16n8k8 B-fragment layout, tf32
__device__ uint2    d_wpk[3 * WPK_N];

// ---------------- tf32 helpers ----------------
__device__ __forceinline__ unsigned f2tf32(float f) {
    unsigned u;
    asm("cvt.rna.tf32.f32 %0, %1;" : "=r"(u) : "f"(f));
    return u;
}

__device__ __forceinline__ void mma_tf32(float c[4], unsigned a0, unsigned a1,
                                         unsigned a2, unsigned a3,
                                         unsigned b0, unsigned b1) {
    asm volatile(
        "mma.sync.aligned.m16n8k8.row.col.f32.tf32.tf32.f32 "
        "{%0,%1,%2,%3}, {%4,%5,%6,%7}, {%8,%9}, {%0,%1,%2,%3};"
        : "+f"(c[0]), "+f"(c[1]), "+f"(c[2]), "+f"(c[3])
        : "r"(a0), "r"(a1), "r"(a2), "r"(a3), "r"(b0), "r"(b1));
}

// ---------------- setup: zero counters + pack W fragments --------------------
__global__ void k_zero_pack(const float* __restrict__ W1, const float* __restrict__ W2,
                            const float* __restrict__ W3) {
    int i = blockIdx.x * blockDim.x + threadIdx.x;
    if (i < N_NODES) d_deg[i] = 0;
    if (i < NGRAPH)  d_gcount[i] = 0;
    if (i < 3 * WPK_N) {
        int m    = i / WPK_N;
        int rem  = i - m * WPK_N;
        int ks   = rem >> 9;
        int nt   = (rem >> 5) & 15;
        int lane = rem & 31;
        int q = lane & 3, g = lane >> 2;
        const float* W = (m == 0) ? W1 : (m == 1) ? W2 : W3;
        int k = ks * 8 + q;
        int n = nt * 8 + g;
        uint2 u;
        u.x = f2tf32(W[k * CH + n]);
        u.y = f2tf32(W[(k + 4) * CH + n]);
        d_wpk[i] = u;
    }
}

// ---------------- hist + x->bf16 convert (800000 threads, exact match) -------
__global__ void k_hist(const int* __restrict__ dst, const int* __restrict__ batch,
                       const float* __restrict__ x) {
    int i = blockIdx.x * blockDim.x + threadIdx.x;
    if (i >= N_EDGES) return;
    atomicAdd(&d_deg[dst[i]], 1);
    if (i < N_NODES) atomicAdd(&d_gcount[batch[i]], 1);
    float4 v0 = ((const float4*)x)[i * 2];
    float4 v1 = ((const float4*)x)[i * 2 + 1];
    __nv_bfloat162 p0 = __floats2bfloat162_rn(v0.x, v0.y);
    __nv_bfloat162 p1 = __floats2bfloat162_rn(v0.z, v0.w);
    __nv_bfloat162 p2 = __floats2bfloat162_rn(v1.x, v1.y);
    __nv_bfloat162 p3 = __floats2bfloat162_rn(v1.z, v1.w);
    uint4 u;
    u.x = *reinterpret_cast<unsigned*>(&p0);
    u.y = *reinterpret_cast<unsigned*>(&p1);
    u.z = *reinterpret_cast<unsigned*>(&p2);
    u.w = *reinterpret_cast<unsigned*>(&p3);
    d_xb[i] = u;
}

// scanA: warp-shuffle inclusive scan (exact, 2 barriers)
__global__ void k_scanA() {
    __shared__ int wsum[16];
    int t = threadIdx.x;
    int i = blockIdx.x * SCAN_B + t;
    int v = (i < N_NODES) ? d_deg[i] : 0;
    int lane = t & 31;
#pragma unroll
    for (int o = 1; o < 32; o <<= 1) {
        int n = __shfl_up_sync(0xffffffffu, v, o);
        if (lane >= o) v += n;
    }
    if (lane == 31) wsum[t >> 5] = v;
    __syncthreads();
    if (t < 16) {
        int w = wsum[t];
#pragma unroll
        for (int o = 1; o < 16; o <<= 1) {
            int n = __shfl_up_sync(0xffffu, w, o);
            if (t >= o) w += n;
        }
        wsum[t] = w;
    }
    __syncthreads();
    if (t >= 32) v += wsum[(t >> 5) - 1];
    if (i < N_NODES) d_tmp[i] = v;
    if (t == SCAN_B - 1) d_bsum[blockIdx.x] = v;
}

// scanC with inline block-prefix over d_bsum
__global__ void k_scanC() {
    __shared__ int ws[8];
    __shared__ int bpref;
    int t = threadIdx.x;
    int myblk = blockIdx.x >> 1;
    int v = (t < myblk) ? d_bsum[t] : 0;
#pragma unroll
    for (int o = 16; o; o >>= 1) v += __shfl_down_sync(0xffffffffu, v, o);
    if ((t & 31) == 0) ws[t >> 5] = v;
    __syncthreads();
    if (t == 0) {
        int s = 0;
#pragma unroll
        for (int w = 0; w < 8; w++) s += ws[w];
        bpref = s;
    }
    __syncthreads();

    int i = blockIdx.x * 256 + t;
    if (i >= N_NODES) return;
    int incl = d_tmp[i] + bpref;
    int deg  = d_deg[i];
    d_off[i + 1] = incl;
    d_cur[i]     = incl - deg;
    d_dinv[i]    = rsqrtf((float)deg + 1.0f);
    if (i == 0) d_off[0] = 0;
}

__global__ void k_scatter(const int* __restrict__ src, const int* __restrict__ dst) {
    int e = blockIdx.x * blockDim.x + threadIdx.x;
    if (e >= N_EDGES) return;
    int p = atomicAdd(&d_cur[dst[e]], 1);
    d_csr[p] = src[e];
}

// ---------------- GEMM: persistent, B resident, A (bf16) double-buffered -----
__device__ __forceinline__ void prefetch_A(__nv_bfloat16* dstbuf, const uint4* Asrc,
                                           int m0, int tid) {
#pragma unroll
    for (int i = 0; i < 8; i++) {
        int idx = tid + 256 * i;
        int row = idx >> 4;
        int u16 = idx & 15;
        int grow = m0 + row;
        if (grow > N_NODES - 1) grow = N_NODES - 1;
        const uint4* src = Asrc + (size_t)grow * 16 + u16;
        unsigned dst = (unsigned)__cvta_generic_to_shared(dstbuf + row * AH_COLS + u16 * 8);
        asm volatile("cp.async.ca.shared.global [%0], [%1], 16;" :: "r"(dst), "l"(src));
    }
    asm volatile("cp.async.commit_group;" ::: "memory");
}

__global__ __launch_bounds__(256) void k_gemm_persist(int a_sel, int layer) {
    extern __shared__ __nv_bfloat16 dynsmem_h[];
    __nv_bfloat16* AsH = dynsmem_h;
    uint2* Bp = (uint2*)(dynsmem_h + 2 * AH_ELEMS);

    const uint4* Asrc = a_sel ? d_hb : d_xb;

    int tid  = threadIdx.x;
    int wid  = tid >> 5;
    int lane = tid & 31;
    int g    = lane >> 2;
    int q    = lane & 3;
    int wm   = wid * 16;

    {
        const uint4* src4 = (const uint4*)(d_wpk + (size_t)layer * WPK_N);
        uint4* dst4 = (uint4*)Bp;
#pragma unroll
        for (int i = 0; i < 16; i++) dst4[tid + 256 * i] = src4[tid + 256 * i];
    }

    int t0 = blockIdx.x;
    if (t0 < N_TILES) prefetch_A(AsH, Asrc, t0 * 128, tid);

    int buf = 0;
    unsigned* gout = (unsigned*)d_g;   // [N][64] uints (2 bf16 each)

    for (int t = t0; t < N_TILES; t += GEMM_GRID) {
        asm volatile("cp.async.wait_group 0;" ::: "memory");
        __syncthreads();

        int tn = t + GEMM_GRID;
        if (tn < N_TILES) prefetch_A(AsH + (buf ^ 1) * AH_ELEMS, Asrc, tn * 128, tid);

        const unsigned short* Ab = (const unsigned short*)(AsH + buf * AH_ELEMS);
        int m0 = t * 128;

        float acc[16][4];
#pragma unroll
        for (int nt = 0; nt < 16; nt++)
#pragma unroll
            for (int j = 0; j < 4; j++) acc[nt][j] = 0.0f;

#pragma unroll
        for (int ks = 0; ks < 16; ks++) {
            int k8 = ks * 8;
            unsigned a0 = ((unsigned)Ab[(wm + g) * AH_COLS + k8 + q])     << 16;
            unsigned a1 = ((unsigned)Ab[(wm + g + 8) * AH_COLS + k8 + q]) << 16;
            unsigned a2 = ((unsigned)Ab[(wm + g) * AH_COLS + k8 + q + 4]) << 16;
            unsigned a3 = ((unsigned)Ab[(wm + g + 8) * AH_COLS + k8 + q + 4]) << 16;
#pragma unroll
            for (int nt = 0; nt < 16; nt++) {
                uint2 b = Bp[(ks * 16 + nt) * 32 + lane];
                mma_tf32(acc[nt], a0, a1, a2, a3, b.x, b.y);
            }
        }

        int r0 = m0 + wm + g;
        int r1 = r0 + 8;
        bool v0 = (r0 < N_NODES);
        bool v1 = (r1 < N_NODES);
        float s0 = v0 ? d_dinv[r0] : 0.0f;
        float s1 = v1 ? d_dinv[r1] : 0.0f;
#pragma unroll
        for (int nt = 0; nt < 16; nt++) {
            int cu = nt * 4 + q;
            if (v0) {
                __nv_bfloat162 p = __floats2bfloat162_rn(s0 * acc[nt][0], s0 * acc[nt][1]);
                gout[(size_t)r0 * 64 + cu] = *reinterpret_cast<unsigned*>(&p);
            }
            if (v1) {
                __nv_bfloat162 p = __floats2bfloat162_rn(s1 * acc[nt][2], s1 * acc[nt][3]);
                gout[(size_t)r1 * 64 + cu] = *reinterpret_cast<unsigned*>(&p);
            }
        }

        __syncthreads();
        buf ^= 1;
    }
}

// ---------------- aggregation: h = relu(dinv_i * (g_i + Σ g_src) + b) --------
__device__ __forceinline__ float4 ld_g(int row, int lane) {
    uint2 u = __ldg(&d_g[(size_t)row * 32 + lane]);
    float2 f0 = __bfloat1622float2(*reinterpret_cast<__nv_bfloat162*>(&u.x));
    float2 f1 = __bfloat1622float2(*reinterpret_cast<__nv_bfloat162*>(&u.y));
    return make_float4(f0.x, f0.y, f1.x, f1.y);
}

__global__ __launch_bounds__(256) void k_agg(const float* __restrict__ bias) {
    int gw = (blockIdx.x * blockDim.x + threadIdx.x) >> 5;
    if (gw >= N_NODES) return;
    int lane = threadIdx.x & 31;

    int beg = d_off[gw];
    int end = d_off[gw + 1];

    float4 acc = ld_g(gw, lane);   // self term
    int j = beg;
    for (; j + 8 <= end; j += 8) {
        int s0 = d_csr[j + 0];
        int s1 = d_csr[j + 1];
        int s2 = d_csr[j + 2];
        int s3 = d_csr[j + 3];
        int s4 = d_csr[j + 4];
        int s5 = d_csr[j + 5];
        int s6 = d_csr[j + 6];
        int s7 = d_csr[j + 7];
        float4 a0 = ld_g(s0, lane);
        float4 a1 = ld_g(s1, lane);
        float4 a2 = ld_g(s2, lane);
        float4 a3 = ld_g(s3, lane);
        float4 a4 = ld_g(s4, lane);
        float4 a5 = ld_g(s5, lane);
        float4 a6 = ld_g(s6, lane);
        float4 a7 = ld_g(s7, lane);
        acc.x += ((a0.x + a1.x) + (a2.x + a3.x)) + ((a4.x + a5.x) + (a6.x + a7.x));
        acc.y += ((a0.y + a1.y) + (a2.y + a3.y)) + ((a4.y + a5.y) + (a6.y + a7.y));
        acc.z += ((a0.z + a1.z) + (a2.z + a3.z)) + ((a4.z + a5.z) + (a6.z + a7.z));
        acc.w += ((a0.w + a1.w) + (a2.w + a3.w)) + ((a4.w + a5.w) + (a6.w + a7.w));
    }
    for (; j < end; j++) {
        float4 a = ld_g(d_csr[j], lane);
        acc.x += a.x; acc.y += a.y; acc.z += a.z; acc.w += a.w;
    }

    float  s  = d_dinv[gw];
    float4 b4 = ((const float4*)bias)[lane];
    float rx = fmaxf(fmaf(s, acc.x, b4.x), 0.0f);
    float ry = fmaxf(fmaf(s, acc.y, b4.y), 0.0f);
    float rz = fmaxf(fmaf(s, acc.z, b4.z), 0.0f);
    float rw = fmaxf(fmaf(s, acc.w, b4.w), 0.0f);

    __nv_bfloat162 p0 = __floats2bfloat162_rn(rx, ry);
    __nv_bfloat162 p1 = __floats2bfloat162_rn(rz, rw);
    uint2 u;
    u.x = *reinterpret_cast<unsigned*>(&p0);
    u.y = *reinterpret_cast<unsigned*>(&p1);
    ((uint2*)d_hb)[(size_t)gw * 32 + lane] = u;
}

// ---------------- fused mean-pool + head (512 threads) -----------------------
__global__ __launch_bounds__(512) void k_pool_final(const float* __restrict__ Wc,
                                                    const float* __restrict__ bc,
                                                    float* __restrict__ out) {
    __shared__ float red[4][CH];
    __shared__ float pl[CH];
    __shared__ int rng[2];
    int g = blockIdx.x;
    int t = threadIdx.x;
    if (t == 0) {
        int b = 0;
        for (int j = 0; j < g; j++) b += d_gcount[j];
        rng[0] = b;
        rng[1] = b + d_gcount[g];
    }
    __syncthreads();
    int b = rng[0], e = rng[1];
    int c = t & 127, seg = t >> 7;
    const __nv_bfloat16* h = (const __nv_bfloat16*)d_hb;
    float s = 0.0f;
    for (int i = b + seg; i < e; i += 4) s += __bfloat162float(h[(size_t)i * CH + c]);
    red[seg][c] = s;
    __syncthreads();
    if (seg == 0) {
        float tot = (red[0][c] + red[1][c]) + (red[2][c] + red[3][c]);
        pl[c] = tot / fmaxf((float)(e - b), 1.0f);
    }
    __syncthreads();
    if (t < 64) {
        int o = t >> 5;
        int lane = t & 31;
        float s2 = 0.0f;
#pragma unroll
        for (int k = lane; k < CH; k += 32) s2 += pl[k] * Wc[k * 2 + o];
#pragma unroll
        for (int off = 16; off; off >>= 1) s2 += __shfl_down_sync(0xffffffffu, s2, off);
        if (lane == 0) out[g * 2 + o] = s2 + bc[o];
    }
}

// ---------------- launch -----------------------------------------------------
extern "C" void kernel_launch(void* const* d_in, const int* in_sizes, int n_in,
                              void* d_out, int out_size) {
    const float* x     = (const float*)d_in[0];
    const int*   ei    = (const int*)d_in[1];     // [2, E]: src then dst
    const int*   batch = (const int*)d_in[2];
    const float* W1 = (const float*)d_in[3];
    const float* b1 = (const float*)d_in[4];
    const float* W2 = (const float*)d_in[5];
    const float* b2 = (const float*)d_in[6];
    const float* W3 = (const float*)d_in[7];
    const float* b3 = (const float*)d_in[8];
    const float* Wc = (const float*)d_in[9];
    const float* bc = (const float*)d_in[10];
    float* out = (float*)d_out;

    const int* src = ei;
    const int* dst = ei + N_EDGES;

    // one-time resources for fork-join overlap (no device memory involved)
    static cudaStream_t s2 = nullptr;
    static cudaEvent_t evFork = nullptr, evJoin = nullptr;
    if (!s2) {
        cudaStreamCreateWithFlags(&s2, cudaStreamNonBlocking);
        cudaEventCreateWithFlags(&evFork, cudaEventDisableTiming);
        cudaEventCreateWithFlags(&evJoin, cudaEventDisableTiming);
    }

    cudaFuncSetAttribute(k_gemm_persist, cudaFuncAttributeMaxDynamicSharedMemorySize, GEMM_SMEM);

    int gN = (N_NODES + 255) / 256;
    int gE = (N_EDGES + 255) / 256;
    int gAgg  = (N_NODES * 32 + 255) / 256;

    k_zero_pack<<<gN, 256>>>(W1, W2, W3);
    k_hist<<<gE, 256>>>(dst, batch, x);
    k_scanA<<<NBLK, SCAN_B>>>();
    k_scanC<<<gN, 256>>>();

    // fork: GEMM-1 (needs d_xb, d_wpk, d_dinv) runs concurrently with scatter
    cudaEventRecord(evFork, 0);
    cudaStreamWaitEvent(s2, evFork, 0);
    k_gemm_persist<<<GEMM_GRID, 256, GEMM_SMEM, s2>>>(0, 0);
    cudaEventRecord(evJoin, s2);

    k_scatter<<<gE, 256>>>(src, dst);          // default stream, concurrent

    cudaStreamWaitEvent(0, evJoin, 0);         // join before agg-1
    k_agg<<<gAgg, 256>>>(b1);

    // layer 2
    k_gemm_persist<<<GEMM_GRID, 256, GEMM_SMEM>>>(1, 1);
    k_agg<<<gAgg, 256>>>(b2);
    // layer 3
    k_gemm_persist<<<GEMM_GRID, 256, GEMM_SMEM>>>(1, 2);
    k_agg<<<gAgg, 256>>>(b3);

    k_pool_final<<<NGRAPH, 512>>>(Wc, bc, out);
}

// round 16
// speedup vs baseline: 1.2460x; 1.0270x over previous
#include <cuda_runtime.h>
#include <cuda_bf16.h>

#define N_NODES 50000
#define N_EDGES 800000
#define CH      128
#define NGRAPH  64
#define SCAN_B  512
#define NBLK    ((N_NODES + SCAN_B - 1) / SCAN_B)   // 98
#define WPK_N   (16 * 16 * 32)                       // fragments per layer
#define N_TILES ((N_NODES + 127) / 128)              // 391
#define AH_COLS 136                                  // bf16 cols incl pad
#define AH_ELEMS (128 * AH_COLS)
#define GEMM_SMEM (2 * AH_ELEMS * 2 + WPK_N * 8)     // 69632 + 65536 = 135168
#define GEMM_GRID 148

// ---------------- scratch (__device__ globals; no allocation) ----------------
// NOTE: d_deg / d_gcount rely on zero-init at module load for the FIRST run;
// every run re-zeroes them in k_pool_final's tail, so all graph replays see
// zeroed counters. Deterministic by construction.
__device__ int      d_deg[N_NODES];
__device__ int      d_off[N_NODES + 1];
__device__ int      d_cur[N_NODES];
__device__ int      d_csr[N_EDGES];
__device__ int      d_tmp[N_NODES];
__device__ int      d_bsum[NBLK];
__device__ float    d_dinv[N_NODES];
__device__ int      d_gcount[NGRAPH];
__device__ int      d_gstart[NGRAPH + 1];
__device__ uint2    d_g[N_NODES * 32];        // g = dinv * (h @ W), bf16 (4 ch per uint2)
__device__ uint4    d_xb[N_NODES * CH / 8];   // x in bf16 (converted once)
__device__ uint4    d_hb[N_NODES * CH / 8];   // activations in bf16
// W pre-packed into m16n8k8 B-fragment layout, tf32
__device__ uint2    d_wpk[3 * WPK_N];

// ---------------- tf32 helpers ----------------
__device__ __forceinline__ unsigned f2tf32(float f) {
    unsigned u;
    asm("cvt.rna.tf32.f32 %0, %1;" : "=r"(u) : "f"(f));
    return u;
}

__device__ __forceinline__ void mma_tf32(float c[4], unsigned a0, unsigned a1,
                                         unsigned a2, unsigned a3,
                                         unsigned b0, unsigned b1) {
    asm volatile(
        "mma.sync.aligned.m16n8k8.row.col.f32.tf32.tf32.f32 "
        "{%0,%1,%2,%3}, {%4,%5,%6,%7}, {%8,%9}, {%0,%1,%2,%3};"
        : "+f"(c[0]), "+f"(c[1]), "+f"(c[2]), "+f"(c[3])
        : "r"(a0), "r"(a1), "r"(a2), "r"(a3), "r"(b0), "r"(b1));
}

// ---------------- hist + x->bf16 convert + W pack (800000 threads) -----------
__global__ void k_hist(const int* __restrict__ dst, const int* __restrict__ batch,
                       const float* __restrict__ x,
                       const float* __restrict__ W1, const float* __restrict__ W2,
                       const float* __restrict__ W3) {
    int i = blockIdx.x * blockDim.x + threadIdx.x;
    if (i >= N_EDGES) return;
    atomicAdd(&d_deg[dst[i]], 1);
    if (i < N_NODES) atomicAdd(&d_gcount[batch[i]], 1);
    // x -> bf16 (i covers N_NODES*CH/8 == N_EDGES exactly)
    float4 v0 = ((const float4*)x)[i * 2];
    float4 v1 = ((const float4*)x)[i * 2 + 1];
    __nv_bfloat162 p0 = __floats2bfloat162_rn(v0.x, v0.y);
    __nv_bfloat162 p1 = __floats2bfloat162_rn(v0.z, v0.w);
    __nv_bfloat162 p2 = __floats2bfloat162_rn(v1.x, v1.y);
    __nv_bfloat162 p3 = __floats2bfloat162_rn(v1.z, v1.w);
    uint4 u;
    u.x = *reinterpret_cast<unsigned*>(&p0);
    u.y = *reinterpret_cast<unsigned*>(&p1);
    u.z = *reinterpret_cast<unsigned*>(&p2);
    u.w = *reinterpret_cast<unsigned*>(&p3);
    d_xb[i] = u;
    // W fragment pack (independent of counters)
    if (i < 3 * WPK_N) {
        int m    = i / WPK_N;
        int rem  = i - m * WPK_N;
        int ks   = rem >> 9;
        int nt   = (rem >> 5) & 15;
        int lane = rem & 31;
        int q = lane & 3, g = lane >> 2;
        const float* W = (m == 0) ? W1 : (m == 1) ? W2 : W3;
        int k = ks * 8 + q;
        int n = nt * 8 + g;
        uint2 w;
        w.x = f2tf32(W[k * CH + n]);
        w.y = f2tf32(W[(k + 4) * CH + n]);
        d_wpk[i] = w;
    }
}

// scanA: warp-shuffle inclusive scan + dinv (deg already loaded here)
__global__ void k_scanA() {
    __shared__ int wsum[16];
    int t = threadIdx.x;
    int i = blockIdx.x * SCAN_B + t;
    int deg0 = (i < N_NODES) ? d_deg[i] : 0;
    if (i < N_NODES) d_dinv[i] = rsqrtf((float)deg0 + 1.0f);
    int v = deg0;
    int lane = t & 31;
#pragma unroll
    for (int o = 1; o < 32; o <<= 1) {
        int n = __shfl_up_sync(0xffffffffu, v, o);
        if (lane >= o) v += n;
    }
    if (lane == 31) wsum[t >> 5] = v;
    __syncthreads();
    if (t < 16) {
        int w = wsum[t];
#pragma unroll
        for (int o = 1; o < 16; o <<= 1) {
            int n = __shfl_up_sync(0xffffu, w, o);
            if (t >= o) w += n;
        }
        wsum[t] = w;
    }
    __syncthreads();
    if (t >= 32) v += wsum[(t >> 5) - 1];
    if (i < N_NODES) d_tmp[i] = v;
    if (t == SCAN_B - 1) d_bsum[blockIdx.x] = v;
}

// scanC: inline block-prefix over d_bsum; block 0 also builds d_gstart
__global__ void k_scanC() {
    __shared__ int ws[8];
    __shared__ int bpref;
    __shared__ int gs_w0;
    int t = threadIdx.x;
    int lane = t & 31;
    int myblk = blockIdx.x >> 1;
    int v = (t < myblk) ? d_bsum[t] : 0;
#pragma unroll
    for (int o = 16; o; o >>= 1) v += __shfl_down_sync(0xffffffffu, v, o);
    if (lane == 0) ws[t >> 5] = v;

    // gstart scan (block 0, first 64 threads' data; all threads run shuffles)
    int gc = (blockIdx.x == 0 && t < NGRAPH) ? d_gcount[t] : 0;
    int gv = gc;
#pragma unroll
    for (int o = 1; o < 32; o <<= 1) {
        int n = __shfl_up_sync(0xffffffffu, gv, o);
        if (lane >= o) gv += n;
    }
    __syncthreads();
    if (t == 0) {
        int s = 0;
#pragma unroll
        for (int w = 0; w < 8; w++) s += ws[w];
        bpref = s;
    }
    if (blockIdx.x == 0 && t == 31) gs_w0 = gv;
    __syncthreads();
    if (blockIdx.x == 0 && t < NGRAPH) {
        int incl = gv + ((t >= 32) ? gs_w0 : 0);
        d_gstart[t] = incl - gc;            // exclusive prefix
        if (t == NGRAPH - 1) d_gstart[NGRAPH] = incl;
    }

    int i = blockIdx.x * 256 + t;
    if (i >= N_NODES) return;
    int incl = d_tmp[i] + bpref;
    int deg  = d_deg[i];
    d_off[i + 1] = incl;
    d_cur[i]     = incl - deg;
    if (i == 0) d_off[0] = 0;
}

__global__ void k_scatter(const int* __restrict__ src, const int* __restrict__ dst) {
    int e = blockIdx.x * blockDim.x + threadIdx.x;
    if (e >= N_EDGES) return;
    int p = atomicAdd(&d_cur[dst[e]], 1);
    d_csr[p] = src[e];
}

// ---------------- GEMM: persistent, B resident, A (bf16) double-buffered -----
__device__ __forceinline__ void prefetch_A(__nv_bfloat16* dstbuf, const uint4* Asrc,
                                           int m0, int tid) {
#pragma unroll
    for (int i = 0; i < 8; i++) {
        int idx = tid + 256 * i;
        int row = idx >> 4;
        int u16 = idx & 15;
        int grow = m0 + row;
        if (grow > N_NODES - 1) grow = N_NODES - 1;
        const uint4* src = Asrc + (size_t)grow * 16 + u16;
        unsigned dst = (unsigned)__cvta_generic_to_shared(dstbuf + row * AH_COLS + u16 * 8);
        asm volatile("cp.async.ca.shared.global [%0], [%1], 16;" :: "r"(dst), "l"(src));
    }
    asm volatile("cp.async.commit_group;" ::: "memory");
}

__global__ __launch_bounds__(256) void k_gemm_persist(int a_sel, int layer) {
    extern __shared__ __nv_bfloat16 dynsmem_h[];
    __nv_bfloat16* AsH = dynsmem_h;
    uint2* Bp = (uint2*)(dynsmem_h + 2 * AH_ELEMS);

    const uint4* Asrc = a_sel ? d_hb : d_xb;

    int tid  = threadIdx.x;
    int wid  = tid >> 5;
    int lane = tid & 31;
    int g    = lane >> 2;
    int q    = lane & 3;
    int wm   = wid * 16;

    {
        const uint4* src4 = (const uint4*)(d_wpk + (size_t)layer * WPK_N);
        uint4* dst4 = (uint4*)Bp;
#pragma unroll
        for (int i = 0; i < 16; i++) dst4[tid + 256 * i] = src4[tid + 256 * i];
    }

    int t0 = blockIdx.x;
    if (t0 < N_TILES) prefetch_A(AsH, Asrc, t0 * 128, tid);

    int buf = 0;
    unsigned* gout = (unsigned*)d_g;   // [N][64] uints (2 bf16 each)

    for (int t = t0; t < N_TILES; t += GEMM_GRID) {
        asm volatile("cp.async.wait_group 0;" ::: "memory");
        __syncthreads();

        int tn = t + GEMM_GRID;
        if (tn < N_TILES) prefetch_A(AsH + (buf ^ 1) * AH_ELEMS, Asrc, tn * 128, tid);

        const unsigned short* Ab = (const unsigned short*)(AsH + buf * AH_ELEMS);
        int m0 = t * 128;

        float acc[16][4];
#pragma unroll
        for (int nt = 0; nt < 16; nt++)
#pragma unroll
            for (int j = 0; j < 4; j++) acc[nt][j] = 0.0f;

#pragma unroll
        for (int ks = 0; ks < 16; ks++) {
            int k8 = ks * 8;
            unsigned a0 = ((unsigned)Ab[(wm + g) * AH_COLS + k8 + q])     << 16;
            unsigned a1 = ((unsigned)Ab[(wm + g + 8) * AH_COLS + k8 + q]) << 16;
            unsigned a2 = ((unsigned)Ab[(wm + g) * AH_COLS + k8 + q + 4]) << 16;
            unsigned a3 = ((unsigned)Ab[(wm + g + 8) * AH_COLS + k8 + q + 4]) << 16;
#pragma unroll
            for (int nt = 0; nt < 16; nt++) {
                uint2 b = Bp[(ks * 16 + nt) * 32 + lane];
                mma_tf32(acc[nt], a0, a1, a2, a3, b.x, b.y);
            }
        }

        int r0 = m0 + wm + g;
        int r1 = r0 + 8;
        bool v0 = (r0 < N_NODES);
        bool v1 = (r1 < N_NODES);
        float s0 = v0 ? d_dinv[r0] : 0.0f;
        float s1 = v1 ? d_dinv[r1] : 0.0f;
#pragma unroll
        for (int nt = 0; nt < 16; nt++) {
            int cu = nt * 4 + q;
            if (v0) {
                __nv_bfloat162 p = __floats2bfloat162_rn(s0 * acc[nt][0], s0 * acc[nt][1]);
                gout[(size_t)r0 * 64 + cu] = *reinterpret_cast<unsigned*>(&p);
            }
            if (v1) {
                __nv_bfloat162 p = __floats2bfloat162_rn(s1 * acc[nt][2], s1 * acc[nt][3]);
                gout[(size_t)r1 * 64 + cu] = *reinterpret_cast<unsigned*>(&p);
            }
        }

        __syncthreads();
        buf ^= 1;
    }
}

// ---------------- aggregation: h = relu(dinv_i * (g_i + Σ g_src) + b) --------
__device__ __forceinline__ float4 ld_g(int row, int lane) {
    uint2 u = __ldg(&d_g[(size_t)row * 32 + lane]);
    float2 f0 = __bfloat1622float2(*reinterpret_cast<__nv_bfloat162*>(&u.x));
    float2 f1 = __bfloat1622float2(*reinterpret_cast<__nv_bfloat162*>(&u.y));
    return make_float4(f0.x, f0.y, f1.x, f1.y);
}

__global__ __launch_bounds__(256) void k_agg(const float* __restrict__ bias) {
    int gw = (blockIdx.x * blockDim.x + threadIdx.x) >> 5;
    if (gw >= N_NODES) return;
    int lane = threadIdx.x & 31;

    int beg = d_off[gw];
    int end = d_off[gw + 1];

    float4 acc = ld_g(gw, lane);   // self term
    int j = beg;
    for (; j + 8 <= end; j += 8) {
        int s0 = d_csr[j + 0];
        int s1 = d_csr[j + 1];
        int s2 = d_csr[j + 2];
        int s3 = d_csr[j + 3];
        int s4 = d_csr[j + 4];
        int s5 = d_csr[j + 5];
        int s6 = d_csr[j + 6];
        int s7 = d_csr[j + 7];
        float4 a0 = ld_g(s0, lane);
        float4 a1 = ld_g(s1, lane);
        float4 a2 = ld_g(s2, lane);
        float4 a3 = ld_g(s3, lane);
        float4 a4 = ld_g(s4, lane);
        float4 a5 = ld_g(s5, lane);
        float4 a6 = ld_g(s6, lane);
        float4 a7 = ld_g(s7, lane);
        acc.x += ((a0.x + a1.x) + (a2.x + a3.x)) + ((a4.x + a5.x) + (a6.x + a7.x));
        acc.y += ((a0.y + a1.y) + (a2.y + a3.y)) + ((a4.y + a5.y) + (a6.y + a7.y));
        acc.z += ((a0.z + a1.z) + (a2.z + a3.z)) + ((a4.z + a5.z) + (a6.z + a7.z));
        acc.w += ((a0.w + a1.w) + (a2.w + a3.w)) + ((a4.w + a5.w) + (a6.w + a7.w));
    }
    for (; j < end; j++) {
        float4 a = ld_g(d_csr[j], lane);
        acc.x += a.x; acc.y += a.y; acc.z += a.z; acc.w += a.w;
    }

    float  s  = d_dinv[gw];
    float4 b4 = ((const float4*)bias)[lane];
    float rx = fmaxf(fmaf(s, acc.x, b4.x), 0.0f);
    float ry = fmaxf(fmaf(s, acc.y, b4.y), 0.0f);
    float rz = fmaxf(fmaf(s, acc.z, b4.z), 0.0f);
    float rw = fmaxf(fmaf(s, acc.w, b4.w), 0.0f);

    __nv_bfloat162 p0 = __floats2bfloat162_rn(rx, ry);
    __nv_bfloat162 p1 = __floats2bfloat162_rn(rz, rw);
    uint2 u;
    u.x = *reinterpret_cast<unsigned*>(&p0);
    u.y = *reinterpret_cast<unsigned*>(&p1);
    ((uint2*)d_hb)[(size_t)gw * 32 + lane] = u;
}

// ---------------- fused mean-pool + head + counter re-zero (512 threads) -----
__global__ __launch_bounds__(512) void k_pool_final(const float* __restrict__ Wc,
                                                    const float* __restrict__ bc,
                                                    float* __restrict__ out) {
    __shared__ float red[4][CH];
    __shared__ float pl[CH];
    int g = blockIdx.x;
    int t = threadIdx.x;
    int b = d_gstart[g], e = d_gstart[g + 1];
    int c = t & 127, seg = t >> 7;
    const __nv_bfloat16* h = (const __nv_bfloat16*)d_hb;
    float s = 0.0f;
    for (int i = b + seg; i < e; i += 4) s += __bfloat162float(h[(size_t)i * CH + c]);
    red[seg][c] = s;
    __syncthreads();
    if (seg == 0) {
        float tot = (red[0][c] + red[1][c]) + (red[2][c] + red[3][c]);
        pl[c] = tot / fmaxf((float)(e - b), 1.0f);
    }
    __syncthreads();
    if (t < 64) {
        int o = t >> 5;
        int lane = t & 31;
        float s2 = 0.0f;
#pragma unroll
        for (int k = lane; k < CH; k += 32) s2 += pl[k] * Wc[k * 2 + o];
#pragma unroll
        for (int off = 16; off; off >>= 1) s2 += __shfl_down_sync(0xffffffffu, s2, off);
        if (lane == 0) out[g * 2 + o] = s2 + bc[o];
    }
    // re-zero counters for the next run (gstart already consumed above)
    for (int i = g * 512 + t; i < N_NODES; i += NGRAPH * 512) d_deg[i] = 0;
    if (g == 0 && t < NGRAPH) d_gcount[t] = 0;
}

// ---------------- launch -----------------------------------------------------
extern "C" void kernel_launch(void* const* d_in, const int* in_sizes, int n_in,
                              void* d_out, int out_size) {
    const float* x     = (const float*)d_in[0];
    const int*   ei    = (const int*)d_in[1];     // [2, E]: src then dst
    const int*   batch = (const int*)d_in[2];
    const float* W1 = (const float*)d_in[3];
    const float* b1 = (const float*)d_in[4];
    const float* W2 = (const float*)d_in[5];
    const float* b2 = (const float*)d_in[6];
    const float* W3 = (const float*)d_in[7];
    const float* b3 = (const float*)d_in[8];
    const float* Wc = (const float*)d_in[9];
    const float* bc = (const float*)d_in[10];
    float* out = (float*)d_out;

    const int* src = ei;
    const int* dst = ei + N_EDGES;

    // one-time resources for fork-join overlap (no device memory involved)
    static cudaStream_t s2 = nullptr;
    static cudaEvent_t evFork = nullptr, evJoin = nullptr;
    if (!s2) {
        cudaStreamCreateWithFlags(&s2, cudaStreamNonBlocking);
        cudaEventCreateWithFlags(&evFork, cudaEventDisableTiming);
        cudaEventCreateWithFlags(&evJoin, cudaEventDisableTiming);
    }

    cudaFuncSetAttribute(k_gemm_persist, cudaFuncAttributeMaxDynamicSharedMemorySize, GEMM_SMEM);

    int gN = (N_NODES + 255) / 256;
    int gE = (N_EDGES + 255) / 256;
    int gAgg  = (N_NODES * 32 + 255) / 256;

    k_hist<<<gE, 256>>>(dst, batch, x, W1, W2, W3);
    k_scanA<<<NBLK, SCAN_B>>>();

    // fork: GEMM-1 (needs d_xb, d_wpk, d_dinv — all ready after scanA)
    // overlaps scanC + scatter on the capture stream
    cudaEventRecord(evFork, 0);
    cudaStreamWaitEvent(s2, evFork, 0);
    k_gemm_persist<<<GEMM_GRID, 256, GEMM_SMEM, s2>>>(0, 0);
    cudaEventRecord(evJoin, s2);

    k_scanC<<<gN, 256>>>();
    k_scatter<<<gE, 256>>>(src, dst);

    cudaStreamWaitEvent(0, evJoin, 0);         // join before agg-1
    k_agg<<<gAgg, 256>>>(b1);

    // layer 2
    k_gemm_persist<<<GEMM_GRID, 256, GEMM_SMEM>>>(1, 1);
    k_agg<<<gAgg, 256>>>(b2);
    // layer 3
    k_gemm_persist<<<GEMM_GRID, 256, GEMM_SMEM>>>(1, 2);
    k_agg<<<gAgg, 256>>>(b3);

    k_pool_final<<<NGRAPH, 512>>>(Wc, bc, out);
}